// round 3
// baseline (speedup 1.0000x reference)
#include <cuda_runtime.h>
#include <stdint.h>
#include <math.h>

// Field_64682207478165: instant-NGP hash-grid (L=16, T=2^19, F=2) + MLP 35->32->32->1 (ELU)
// Persistent kernel; levels 0,1 densified into shared memory (bit-identical pre-gather),
// levels 2..15 gathered from L2-resident table.

#define NLVL  16
#define TSZ   (1u << 19)
#define HID   32
#define NFEAT 35
#define R0    16          // level-0 dense grid: s0 = 15.0, corners 0..15
#define R1    21          // level-1 dense grid: s1 = 19.1587, corners 0..20
#define N0    (R0*R0*R0)  // 4096
#define N1    (R1*R1*R1)  // 9261
#define THREADS 512
#define BLOCKS  148

typedef unsigned int u32;

struct LevelScales { float s[NLVL]; };

__device__ __forceinline__ float2 lerp8(float2 g000, float2 g100, float2 g010, float2 g110,
                                        float2 g001, float2 g101, float2 g011, float2 g111,
                                        float wx, float wy, float wz)
{
    const float ux = 1.0f - wx, uy = 1.0f - wy, uz = 1.0f - wz;
    const float w000 = ux*uy*uz, w100 = wx*uy*uz, w010 = ux*wy*uz, w110 = wx*wy*uz;
    const float w001 = ux*uy*wz, w101 = wx*uy*wz, w011 = ux*wy*wz, w111 = wx*wy*wz;
    float a0 = w000 * g000.x, a1 = w000 * g000.y;
    a0 = fmaf(w100, g100.x, a0); a1 = fmaf(w100, g100.y, a1);
    a0 = fmaf(w010, g010.x, a0); a1 = fmaf(w010, g010.y, a1);
    a0 = fmaf(w110, g110.x, a0); a1 = fmaf(w110, g110.y, a1);
    a0 = fmaf(w001, g001.x, a0); a1 = fmaf(w001, g001.y, a1);
    a0 = fmaf(w101, g101.x, a0); a1 = fmaf(w101, g101.y, a1);
    a0 = fmaf(w011, g011.x, a0); a1 = fmaf(w011, g011.y, a1);
    a0 = fmaf(w111, g111.x, a0); a1 = fmaf(w111, g111.y, a1);
    return make_float2(a0, a1);
}

__global__ __launch_bounds__(THREADS, 1) void field_kernel(
    const float* __restrict__ x,
    const float* __restrict__ table,
    const float* __restrict__ W0,
    const float* __restrict__ b0,
    const float* __restrict__ W1,
    const float* __restrict__ b1,
    const float* __restrict__ Wout,
    const float* __restrict__ bout,
    float* __restrict__ out,
    int n, LevelScales sc)
{
    extern __shared__ float smf[];
    float2* d0  = (float2*)smf;            // N0 entries (level 0 dense)
    float2* d1  = d0 + N0;                 // N1 entries (level 1 dense)
    float* sW0  = (float*)(d1 + N1);       // 35*32
    float* sW1  = sW0 + NFEAT*HID;         // 32*32
    float* sB0  = sW1 + HID*HID;
    float* sB1  = sB0 + HID;
    float* sWo  = sB1 + HID;
    float* sBo  = sWo + HID;

    const int tid = threadIdx.x;
    const u32 P1 = 2654435761u, P2 = 805459861u;
    const u32 msk = TSZ - 1u;

    // ---- fill dense coarse levels (values bit-identical to hashed table) ----
    {
        const float2* tb0 = (const float2*)table;
        const float2* tb1 = tb0 + TSZ;
        for (int t = tid; t < N0; t += THREADS) {
            const u32 iz = t & 15u, iy = ((u32)t >> 4) & 15u, ix = (u32)t >> 8;
            d0[t] = __ldg(tb0 + ((ix ^ iy*P1 ^ iz*P2) & msk));
        }
        for (int t = tid; t < N1; t += THREADS) {
            const u32 iz = (u32)t % R1; const u32 r = (u32)t / R1;
            const u32 iy = r % R1, ix = r / R1;
            d1[t] = __ldg(tb1 + ((ix ^ iy*P1 ^ iz*P2) & msk));
        }
        for (int i = tid; i < NFEAT*HID; i += THREADS) sW0[i] = W0[i];
        for (int i = tid; i < HID*HID;   i += THREADS) sW1[i] = W1[i];
        if (tid < HID) { sB0[tid] = b0[tid]; sB1[tid] = b1[tid]; sWo[tid] = Wout[tid]; }
        if (tid == 0)  sBo[0] = bout[0];
    }
    __syncthreads();

    const int stride = gridDim.x * THREADS;
    for (int i = blockIdx.x * THREADS + tid; i < n; i += stride) {

        const float xn0 = (x[3*i + 0] + 1.0f) * 0.5f;
        const float xn1 = (x[3*i + 1] + 1.0f) * 0.5f;
        const float xn2 = (x[3*i + 2] + 1.0f) * 0.5f;

        float feat[NFEAT];
        feat[0] = xn0; feat[1] = xn1; feat[2] = xn2;

        // ---- level 0 from dense smem ----
        {
            const float s = sc.s[0];
            const float px = xn0*s, py = xn1*s, pz = xn2*s;
            const float f0 = floorf(px), f1 = floorf(py), f2 = floorf(pz);
            const float wx = px-f0, wy = py-f1, wz = pz-f2;
            const int ix = (int)f0, iy = (int)f1, iz = (int)f2;
            const int c = (ix*R0 + iy)*R0 + iz;
            float2 r = lerp8(d0[c],            d0[c+R0*R0],        d0[c+R0],        d0[c+R0*R0+R0],
                             d0[c+1],          d0[c+R0*R0+1],      d0[c+R0+1],      d0[c+R0*R0+R0+1],
                             wx, wy, wz);
            feat[3] = r.x; feat[4] = r.y;
        }
        // ---- level 1 from dense smem ----
        {
            const float s = sc.s[1];
            const float px = xn0*s, py = xn1*s, pz = xn2*s;
            const float f0 = floorf(px), f1 = floorf(py), f2 = floorf(pz);
            const float wx = px-f0, wy = py-f1, wz = pz-f2;
            const int ix = (int)f0, iy = (int)f1, iz = (int)f2;
            const int c = (ix*R1 + iy)*R1 + iz;
            float2 r = lerp8(d1[c],            d1[c+R1*R1],        d1[c+R1],        d1[c+R1*R1+R1],
                             d1[c+1],          d1[c+R1*R1+1],      d1[c+R1+1],      d1[c+R1*R1+R1+1],
                             wx, wy, wz);
            feat[5] = r.x; feat[6] = r.y;
        }

        // ---- levels 2..15 hashed from global (L2-resident) ----
        #pragma unroll
        for (int l = 2; l < NLVL; ++l) {
            const float s = sc.s[l];
            const float px = xn0*s, py = xn1*s, pz = xn2*s;
            const float f0 = floorf(px), f1 = floorf(py), f2 = floorf(pz);
            const float wx = px-f0, wy = py-f1, wz = pz-f2;
            const u32 ix = (u32)(int)f0, iy = (u32)(int)f1, iz = (u32)(int)f2;

            const u32 hx0 = ix,      hx1 = ix + 1u;
            const u32 hy0 = iy * P1, hy1 = (iy + 1u) * P1;
            const u32 hz0 = iz * P2, hz1 = (iz + 1u) * P2;

            const float2* __restrict__ tb = ((const float2*)table) + (size_t)l * TSZ;

            const float2 g000 = __ldg(tb + ((hx0 ^ hy0 ^ hz0) & msk));
            const float2 g100 = __ldg(tb + ((hx1 ^ hy0 ^ hz0) & msk));
            const float2 g010 = __ldg(tb + ((hx0 ^ hy1 ^ hz0) & msk));
            const float2 g110 = __ldg(tb + ((hx1 ^ hy1 ^ hz0) & msk));
            const float2 g001 = __ldg(tb + ((hx0 ^ hy0 ^ hz1) & msk));
            const float2 g101 = __ldg(tb + ((hx1 ^ hy0 ^ hz1) & msk));
            const float2 g011 = __ldg(tb + ((hx0 ^ hy1 ^ hz1) & msk));
            const float2 g111 = __ldg(tb + ((hx1 ^ hy1 ^ hz1) & msk));

            float2 r = lerp8(g000,g100,g010,g110,g001,g101,g011,g111, wx,wy,wz);
            feat[3 + 2*l]     = r.x;
            feat[3 + 2*l + 1] = r.y;
        }

        // ---- MLP ----
        float h1[HID];
        #pragma unroll
        for (int j = 0; j < HID; ++j) h1[j] = sB0[j];
        #pragma unroll
        for (int k = 0; k < NFEAT; ++k) {
            const float f = feat[k];
            #pragma unroll
            for (int j = 0; j < HID; ++j)
                h1[j] = fmaf(f, sW0[k*HID + j], h1[j]);
        }
        #pragma unroll
        for (int j = 0; j < HID; ++j)
            h1[j] = (h1[j] > 0.0f) ? h1[j] : (__expf(h1[j]) - 1.0f);

        float h2[HID];
        #pragma unroll
        for (int j = 0; j < HID; ++j) h2[j] = sB1[j];
        #pragma unroll
        for (int k = 0; k < HID; ++k) {
            const float f = h1[k];
            #pragma unroll
            for (int j = 0; j < HID; ++j)
                h2[j] = fmaf(f, sW1[k*HID + j], h2[j]);
        }
        #pragma unroll
        for (int j = 0; j < HID; ++j)
            h2[j] = (h2[j] > 0.0f) ? h2[j] : (__expf(h2[j]) - 1.0f);

        float acc = sBo[0];
        #pragma unroll
        for (int j = 0; j < HID; ++j) acc = fmaf(h2[j], sWo[j], acc);

        out[i] = acc;
    }
}

extern "C" void kernel_launch(void* const* d_in, const int* in_sizes, int n_in,
                              void* d_out, int out_size)
{
    const float* x     = (const float*)d_in[0];
    const float* table = (const float*)d_in[1];
    const float* W0    = (const float*)d_in[2];
    const float* b0    = (const float*)d_in[3];
    const float* W1    = (const float*)d_in[4];
    const float* b1    = (const float*)d_in[5];
    const float* Wout  = (const float*)d_in[6];
    const float* bout  = (const float*)d_in[7];
    float* out = (float*)d_out;

    const int n = in_sizes[0] / 3;

    LevelScales sc;
    const double B = exp(log(512.0 / 16.0) / 15.0);   // 2^(1/3)
    for (int l = 0; l < NLVL; ++l)
        sc.s[l] = (float)(16.0 * pow(B, (double)l) - 1.0);

    const size_t smem = (size_t)(N0 + N1) * sizeof(float2)
                      + (size_t)(NFEAT*HID + HID*HID + 3*HID + 1) * sizeof(float);

    cudaFuncSetAttribute(field_kernel, cudaFuncAttributeMaxDynamicSharedMemorySize, (int)smem);
    field_kernel<<<BLOCKS, THREADS, smem>>>(x, table, W0, b0, W1, b1, Wout, bout, out, n, sc);
}

// round 4
// speedup vs baseline: 1.5103x; 1.5103x over previous
#include <cuda_runtime.h>
#include <stdint.h>
#include <math.h>

// Field_64682207478165: instant-NGP hash-grid (L=16, T=2^19, F=2) + MLP 35->32->32->1 (ELU)
// Strategy: Morton-bucket counting sort of points (locality => corner-LDG line sharing
// within warps => fewer l1tex wavefronts), then fused encode+MLP kernel on sorted points.

#define NLVL  16
#define TSZ   (1u << 19)
#define HID   32
#define NFEAT 35
#define NB    32768          // 32^3 Morton buckets @ 1/64 granularity over [0.5,1)
#define MAXN  2097152

typedef unsigned int u32;

struct LevelScales { float s[NLVL]; };

__device__ float4 g_xs[MAXN];     // sorted (xn0, xn1, xn2, idx-as-bits)
__device__ u32    g_hist[NB];

__device__ __forceinline__ u32 expand3(u32 v) {   // 5 bits -> every 3rd bit
    v = (v | (v << 8)) & 0x0300Fu;
    v = (v | (v << 4)) & 0x030C3u;
    v = (v | (v << 2)) & 0x09249u;
    return v;
}

__device__ __forceinline__ u32 bucket_key(float xn0, float xn1, float xn2) {
    int ix = (int)((xn0 - 0.5f) * 64.0f);
    int iy = (int)((xn1 - 0.5f) * 64.0f);
    int iz = (int)((xn2 - 0.5f) * 64.0f);
    ix = min(31, max(0, ix)); iy = min(31, max(0, iy)); iz = min(31, max(0, iz));
    return expand3((u32)ix) | (expand3((u32)iy) << 1) | (expand3((u32)iz) << 2);
}

__global__ void zero_hist_kernel() {
    int i = blockIdx.x * blockDim.x + threadIdx.x;
    if (i < NB) g_hist[i] = 0u;
}

__global__ void hist_kernel(const float* __restrict__ x, int n) {
    int i = blockIdx.x * blockDim.x + threadIdx.x;
    if (i >= n) return;
    const float xn0 = (x[3*i+0] + 1.0f) * 0.5f;
    const float xn1 = (x[3*i+1] + 1.0f) * 0.5f;
    const float xn2 = (x[3*i+2] + 1.0f) * 0.5f;
    atomicAdd(&g_hist[bucket_key(xn0, xn1, xn2)], 1u);
}

__global__ void scan_kernel() {           // exclusive scan of g_hist, single block 1024 thr
    __shared__ u32 s[1024];
    const int tid = threadIdx.x;
    u32 run = 0;
    for (int c = 0; c < NB / 1024; ++c) {
        const int idx = c * 1024 + tid;
        const u32 v = g_hist[idx];
        s[tid] = v;
        __syncthreads();
        #pragma unroll
        for (int off = 1; off < 1024; off <<= 1) {
            u32 t = (tid >= off) ? s[tid - off] : 0u;
            __syncthreads();
            s[tid] += t;
            __syncthreads();
        }
        g_hist[idx] = run + s[tid] - v;     // exclusive
        const u32 total = s[1023];
        __syncthreads();
        run += total;
    }
}

__global__ void scatter_kernel(const float* __restrict__ x, int n) {
    int i = blockIdx.x * blockDim.x + threadIdx.x;
    if (i >= n) return;
    const float xn0 = (x[3*i+0] + 1.0f) * 0.5f;
    const float xn1 = (x[3*i+1] + 1.0f) * 0.5f;
    const float xn2 = (x[3*i+2] + 1.0f) * 0.5f;
    const u32 pos = atomicAdd(&g_hist[bucket_key(xn0, xn1, xn2)], 1u);
    g_xs[pos] = make_float4(xn0, xn1, xn2, __int_as_float(i));
}

__device__ __forceinline__ float2 lerp8(float2 g000, float2 g100, float2 g010, float2 g110,
                                        float2 g001, float2 g101, float2 g011, float2 g111,
                                        float wx, float wy, float wz)
{
    const float ux = 1.0f - wx, uy = 1.0f - wy, uz = 1.0f - wz;
    const float w000 = ux*uy*uz, w100 = wx*uy*uz, w010 = ux*wy*uz, w110 = wx*wy*uz;
    const float w001 = ux*uy*wz, w101 = wx*uy*wz, w011 = ux*wy*wz, w111 = wx*wy*wz;
    float a0 = w000 * g000.x, a1 = w000 * g000.y;
    a0 = fmaf(w100, g100.x, a0); a1 = fmaf(w100, g100.y, a1);
    a0 = fmaf(w010, g010.x, a0); a1 = fmaf(w010, g010.y, a1);
    a0 = fmaf(w110, g110.x, a0); a1 = fmaf(w110, g110.y, a1);
    a0 = fmaf(w001, g001.x, a0); a1 = fmaf(w001, g001.y, a1);
    a0 = fmaf(w101, g101.x, a0); a1 = fmaf(w101, g101.y, a1);
    a0 = fmaf(w011, g011.x, a0); a1 = fmaf(w011, g011.y, a1);
    a0 = fmaf(w111, g111.x, a0); a1 = fmaf(w111, g111.y, a1);
    return make_float2(a0, a1);
}

template<bool SORTED>
__global__ __launch_bounds__(256, 2) void field_kernel(
    const float* __restrict__ x,
    const float* __restrict__ table,
    const float* __restrict__ W0,
    const float* __restrict__ b0,
    const float* __restrict__ W1,
    const float* __restrict__ b1,
    const float* __restrict__ Wout,
    const float* __restrict__ bout,
    float* __restrict__ out,
    int n, LevelScales sc)
{
    __shared__ float sW0[NFEAT * HID];
    __shared__ float sW1[HID * HID];
    __shared__ float sB0[HID], sB1[HID], sWo[HID];
    __shared__ float sBo;

    const int tid = threadIdx.x;
    for (int i = tid; i < NFEAT * HID; i += 256) sW0[i] = W0[i];
    for (int i = tid; i < HID * HID;   i += 256) sW1[i] = W1[i];
    if (tid < HID) { sB0[tid] = b0[tid]; sB1[tid] = b1[tid]; sWo[tid] = Wout[tid]; }
    if (tid == 0) sBo = bout[0];
    __syncthreads();

    const int i = blockIdx.x * 256 + tid;
    if (i >= n) return;

    float xn0, xn1, xn2;
    int oidx;
    if (SORTED) {
        const float4 p = g_xs[i];
        xn0 = p.x; xn1 = p.y; xn2 = p.z; oidx = __float_as_int(p.w);
    } else {
        xn0 = (x[3*i+0] + 1.0f) * 0.5f;
        xn1 = (x[3*i+1] + 1.0f) * 0.5f;
        xn2 = (x[3*i+2] + 1.0f) * 0.5f;
        oidx = i;
    }

    float feat[NFEAT];
    feat[0] = xn0; feat[1] = xn1; feat[2] = xn2;

    const u32 P1 = 2654435761u, P2 = 805459861u;
    const u32 msk = TSZ - 1u;

    #pragma unroll
    for (int l = 0; l < NLVL; ++l) {
        const float s = sc.s[l];
        const float px = xn0 * s, py = xn1 * s, pz = xn2 * s;
        const float f0 = floorf(px), f1 = floorf(py), f2 = floorf(pz);
        const float wx = px - f0, wy = py - f1, wz = pz - f2;
        const u32 ix = (u32)f0, iy = (u32)f1, iz = (u32)f2;

        const u32 hx0 = ix,      hx1 = ix + 1u;
        const u32 hy0 = iy * P1, hy1 = (iy + 1u) * P1;
        const u32 hz0 = iz * P2, hz1 = (iz + 1u) * P2;

        const float2* __restrict__ tb = ((const float2*)table) + (size_t)l * TSZ;

        const float2 g000 = __ldg(tb + ((hx0 ^ hy0 ^ hz0) & msk));
        const float2 g100 = __ldg(tb + ((hx1 ^ hy0 ^ hz0) & msk));
        const float2 g010 = __ldg(tb + ((hx0 ^ hy1 ^ hz0) & msk));
        const float2 g110 = __ldg(tb + ((hx1 ^ hy1 ^ hz0) & msk));
        const float2 g001 = __ldg(tb + ((hx0 ^ hy0 ^ hz1) & msk));
        const float2 g101 = __ldg(tb + ((hx1 ^ hy0 ^ hz1) & msk));
        const float2 g011 = __ldg(tb + ((hx0 ^ hy1 ^ hz1) & msk));
        const float2 g111 = __ldg(tb + ((hx1 ^ hy1 ^ hz1) & msk));

        float2 r = lerp8(g000,g100,g010,g110,g001,g101,g011,g111, wx,wy,wz);
        feat[3 + 2*l]     = r.x;
        feat[3 + 2*l + 1] = r.y;
    }

    // ---- MLP ----
    float h1[HID];
    #pragma unroll
    for (int j = 0; j < HID; ++j) h1[j] = sB0[j];
    #pragma unroll
    for (int k = 0; k < NFEAT; ++k) {
        const float f = feat[k];
        #pragma unroll
        for (int j = 0; j < HID; ++j)
            h1[j] = fmaf(f, sW0[k * HID + j], h1[j]);
    }
    #pragma unroll
    for (int j = 0; j < HID; ++j)
        h1[j] = (h1[j] > 0.0f) ? h1[j] : (__expf(h1[j]) - 1.0f);

    float h2[HID];
    #pragma unroll
    for (int j = 0; j < HID; ++j) h2[j] = sB1[j];
    #pragma unroll
    for (int k = 0; k < HID; ++k) {
        const float f = h1[k];
        #pragma unroll
        for (int j = 0; j < HID; ++j)
            h2[j] = fmaf(f, sW1[k * HID + j], h2[j]);
    }
    #pragma unroll
    for (int j = 0; j < HID; ++j)
        h2[j] = (h2[j] > 0.0f) ? h2[j] : (__expf(h2[j]) - 1.0f);

    float acc = sBo;
    #pragma unroll
    for (int j = 0; j < HID; ++j) acc = fmaf(h2[j], sWo[j], acc);

    out[oidx] = acc;
}

extern "C" void kernel_launch(void* const* d_in, const int* in_sizes, int n_in,
                              void* d_out, int out_size)
{
    const float* x     = (const float*)d_in[0];
    const float* table = (const float*)d_in[1];
    const float* W0    = (const float*)d_in[2];
    const float* b0    = (const float*)d_in[3];
    const float* W1    = (const float*)d_in[4];
    const float* b1    = (const float*)d_in[5];
    const float* Wout  = (const float*)d_in[6];
    const float* bout  = (const float*)d_in[7];
    float* out = (float*)d_out;

    const int n = in_sizes[0] / 3;

    LevelScales sc;
    const double B = exp(log(512.0 / 16.0) / 15.0);   // 2^(1/3)
    for (int l = 0; l < NLVL; ++l)
        sc.s[l] = (float)(16.0 * pow(B, (double)l) - 1.0);

    const int blocks = (n + 255) / 256;

    if (n <= MAXN) {
        zero_hist_kernel<<<(NB + 255) / 256, 256>>>();
        hist_kernel<<<blocks, 256>>>(x, n);
        scan_kernel<<<1, 1024>>>();
        scatter_kernel<<<blocks, 256>>>(x, n);
        field_kernel<true><<<blocks, 256>>>(x, table, W0, b0, W1, b1, Wout, bout, out, n, sc);
    } else {
        field_kernel<false><<<blocks, 256>>>(x, table, W0, b0, W1, b1, Wout, bout, out, n, sc);
    }
}